// round 15
// baseline (speedup 1.0000x reference)
#include <cuda_runtime.h>
#include <cstdint>

// Problem constants (from reference)
#define DD   41
#define CCH  64
#define CHT  105          // DD + CCH
#define FH_  32
#define FW_  88
#define B_   4
#define NX0_ 200
#define NZ_  200
#define COLH (CHT * FH_)  // 3360 floats per (b,w) column
#define FOFF (DD * FH_)   // 1312: feature slab offset within a column
#define OUTN  (B_ * CCH * NZ_ * NX0_)   // 10,240,000 floats
#define NA   (FW_ * B_)   // 352 mainA blocks

// Static scratch
__device__ float g_xT[(size_t)B_ * FW_ * COLH];          // 4.73 MB
__device__ float g_wts[(size_t)NA * DD * FH_];           // final weights 1.85 MB
__device__ int   g_binh[(size_t)NA * DD * FH_];          // per-h bins    1.85 MB
__device__ int   g_binsp[NA * DD];                       // uniform bin
__device__ int   g_flags[NA * DD];                       // 0/1/2

// ---------------------------------------------------------------------------
// Kernel 1: layout transform (R14-proven tiles, zero-fill REMOVED).
//   blockIdx.x <  41 : logit tile  -> xT[b][w][d*32+h]
//   blockIdx.x >= 41 : feature tile -> xT[b][w][1312 + h*64 + c]
// ---------------------------------------------------------------------------
__global__ __launch_bounds__(256) void lss_T(const float* __restrict__ x) {
    __shared__ float tile[32][33];
    const int tx = threadIdx.x & 31;
    const int ty = threadIdx.x >> 5;
    const int b  = blockIdx.z;
    const int c0 = blockIdx.y * 32;   // w-tile base
    const float* xb = x + (size_t)b * COLH * FW_;
    float* xt = g_xT + (size_t)b * FW_ * COLH;

    if (blockIdx.x < 41) {
        const int r0 = blockIdx.x * 32;
#pragma unroll
        for (int i = ty; i < 32; i += 8) {
            int r = r0 + i, c = c0 + tx;
            if (c < FW_) tile[i][tx] = xb[(size_t)r * FW_ + c];
        }
        __syncthreads();
#pragma unroll
        for (int i = ty; i < 32; i += 8) {
            int w = c0 + i, r = r0 + tx;
            if (w < FW_) xt[(size_t)w * COLH + r] = tile[tx][i];
        }
    } else {
        const int idx = blockIdx.x - 41;      // 0..63
        const int h   = idx >> 1;
        const int cg  = idx & 1;
#pragma unroll
        for (int i = ty; i < 32; i += 8) {
            int row = (DD + cg * 32 + i) * FH_ + h;
            int c = c0 + tx;
            if (c < FW_) tile[i][tx] = xb[(size_t)row * FW_ + c];
        }
        __syncthreads();
#pragma unroll
        for (int j = ty; j < 32; j += 8) {
            int w = c0 + j;
            if (w < FW_)
                xt[(size_t)w * COLH + FOFF + h * CCH + cg * 32 + tx] = tile[tx][j];
        }
    }
}

// ---------------------------------------------------------------------------
// Kernel 2 (mainA): zero-fill (hidden under front-end) + softmax + geometry.
// One block per (w, b). Writes weights/bins/flags to scratch. The kernel
// boundary orders ALL zero stores before mainB's atomics — no fence needed.
// ---------------------------------------------------------------------------
__global__ __launch_bounds__(256) void lss_mainA(
    const float* __restrict__ intrins,
    const float* __restrict__ rots,
    const float* __restrict__ trans,
    float* __restrict__ out)
{
    __shared__ float wts[DD][FH_];      // logits -> exp(v - m_g)
    __shared__ float pm[8][FH_];
    __shared__ float ps[8][FH_];
    __shared__ float scale[8][FH_];
    __shared__ float iR[9], iK[9], tv[3];

    const int w    = blockIdx.x;
    const int b    = blockIdx.y;
    const int tid  = threadIdx.x;
    const int lane = tid & 31;
    const int wg   = tid >> 5;
    const int blk  = b * FW_ + w;

    // P0: zero my 1/352 slice of out. Fire-and-forget STG.128 — drains on
    // the HBM write path while the ALU/MUFU front-end below executes.
    {
        float4* o4 = (float4*)out;
        const int n4 = OUTN / 4;
        const float4 z4 = make_float4(0.f, 0.f, 0.f, 0.f);
        for (int i = blk * 256 + tid; i < n4; i += NA * 256) o4[i] = z4;
    }

    const float* xt = g_xT + (size_t)blk * COLH;

    // P1a: logits -> smem (contiguous float4)
    {
        const float4* src = (const float4*)xt;
        float4* dst = (float4*)&wts[0][0];
        for (int i = tid; i < FOFF / 4; i += 256) dst[i] = src[i];
    }
    // P1b: PARALLEL 3x3 inversions (one correctly-rounded division each).
    if (tid < 18) {
        const int which = tid / 9;
        const int e     = tid % 9;
        const float* mm = which ? (intrins + b * 9) : (rots + b * 9);
        float a0 = mm[0], a1 = mm[1], a2 = mm[2];
        float a3 = mm[3], a4 = mm[4], a5 = mm[5];
        float a6 = mm[6], a7 = mm[7], a8 = mm[8];
        float c00 = a4 * a8 - a5 * a7;
        float c01 = a5 * a6 - a3 * a8;
        float c02 = a3 * a7 - a4 * a6;
        float det = a0 * c00 + a1 * c01 + a2 * c02;
        float num;
        switch (e) {
            case 0: num = c00; break;
            case 1: num = a2 * a7 - a1 * a8; break;
            case 2: num = a1 * a5 - a2 * a4; break;
            case 3: num = c01; break;
            case 4: num = a0 * a8 - a2 * a6; break;
            case 5: num = a2 * a3 - a0 * a5; break;
            case 6: num = c02; break;
            case 7: num = a1 * a6 - a0 * a7; break;
            default: num = a0 * a4 - a1 * a3; break;
        }
        float r = __fdiv_rn(num, det);
        if (which) iK[e] = r; else iR[e] = r;
    }
    if (tid < 3) tv[tid] = trans[b * 3 + tid];
    __syncthreads();

    // P2: single-pass group softmax. Thread (wg, lane): d = wg + 8k.
    {
        float m_t = -3.402823466e38f;
        for (int d = wg; d < DD; d += 8) m_t = fmaxf(m_t, wts[d][lane]);
        float s_t = 0.f;
        for (int d = wg; d < DD; d += 8) {
            float e = __expf(wts[d][lane] - m_t);
            wts[d][lane] = e;
            s_t += e;
        }
        pm[wg][lane] = m_t;
        ps[wg][lane] = s_t;
    }
    __syncthreads();
    if (tid < 32) {
        float m = pm[0][lane];
#pragma unroll
        for (int g = 1; g < 8; g++) m = fmaxf(m, pm[g][lane]);
        float s = 0.f;
#pragma unroll
        for (int g = 0; g < 8; g++) s += ps[g][lane] * __expf(pm[g][lane] - m);
        float rinv = __frcp_rn(s);
#pragma unroll
        for (int g = 0; g < 8; g++) scale[g][lane] = __expf(pm[g][lane] - m) * rinv;
    }
    __syncthreads();

    // P3: geometry. warp wg handles d = wg, wg+8, ...; lane = h.
    // Final weights/bins go STRAIGHT to scratch (coalesced 128B warp stores).
    {
        const float xs = (float)w    * (703.0f / 87.0f);
        const float ys = (float)lane * (255.0f / 31.0f);
        const float r00 = iR[0], r01 = iR[1], r02 = iR[2];
        const float r10 = iR[3], r11 = iR[4], r12 = iR[5];
        const float r20 = iR[6], r21 = iR[7], r22 = iR[8];
        const float k00 = iK[0], k01 = iK[1], k02 = iK[2];
        const float k10 = iK[3], k11 = iK[4], k12 = iK[5];
        const float k20 = iK[6], k21 = iK[7], k22 = iK[8];
        const float t0 = tv[0], t1 = tv[1], t2 = tv[2];
        const float p0 = xs - t0, p1 = ys - t1;
        const float sc = scale[wg][lane];

        float* wout = g_wts + (size_t)blk * DD * FH_;
        int*   bout = g_binh + (size_t)blk * DD * FH_;

        for (int d = wg; d < DD; d += 8) {
            float p2 = (4.0f + (float)d) - t2;
            float q0 = __fmaf_rn(r00, p0, __fmaf_rn(r01, p1, r02 * p2));
            float q1 = __fmaf_rn(r10, p0, __fmaf_rn(r11, p1, r12 * p2));
            float q2 = __fmaf_rn(r20, p0, __fmaf_rn(r21, p1, r22 * p2));
            float s0 = q0 * q2, s1 = q1 * q2, s2 = q2;
            float g0 = __fmaf_rn(k00, s0, __fmaf_rn(k01, s1, k02 * s2));
            float g1 = __fmaf_rn(k10, s0, __fmaf_rn(k11, s1, k12 * s2));
            float g2 = __fmaf_rn(k20, s0, __fmaf_rn(k21, s1, k22 * s2));
            // truncation toward zero matches astype(int32)
            int c0i = (int)((g0 + 50.0f) / 0.5f);
            int c1i = (int)((g1 + 10.0f) / 20.0f);
            int c2i = (int)(g2 / 0.25f);
            bool kept = (c0i >= 0) & (c0i < NX0_) & (c1i >= 0) & (c1i < 1) &
                        (c2i >= 0) & (c2i < NZ_);
            int sp = c2i * NX0_ + c0i;
            float wv = kept ? wts[d][lane] * sc : 0.0f;

            wout[d * FH_ + lane] = wv;      // coalesced
            bout[d * FH_ + lane] = sp;      // coalesced

            unsigned km = __ballot_sync(0xffffffffu, kept);
            int fl = 0;
            int lsp = 0;
            if (km) {
                int src = __ffs(km) - 1;
                lsp = __shfl_sync(0xffffffffu, sp, src);
                bool ok = (!kept) || (sp == lsp);
                fl = __all_sync(0xffffffffu, ok) ? 1 : 2;
            }
            if (lane == 0) {
                g_flags[blk * DD + d] = fl;
                g_binsp[blk * DD + d] = lsp;
            }
        }
    }
}

// ---------------------------------------------------------------------------
// Kernel 3 (mainB): gather + scatter. One block per (w, b, chalf), 256 thr,
// NO smem, NO barriers. All zero stores from mainA are retired (kernel
// boundary), so atomics are safe.
// ---------------------------------------------------------------------------
__global__ __launch_bounds__(256) void lss_mainB(float* __restrict__ out) {
    const int w     = blockIdx.x;
    const int b     = blockIdx.y;
    const int chalf = blockIdx.z;              // 0 or 1
    const int tid   = threadIdx.x;
    const int lane  = tid & 31;
    const int wg    = tid >> 5;                // 0..7 -> d group
    const int c     = chalf * 32 + lane;
    const int blk   = b * FW_ + w;

    // f[32]: coalesced (lanes = consecutive c => one 128B line per h)
    float f[FH_];
    {
        const float* xf = g_xT + (size_t)blk * COLH + FOFF + c;
#pragma unroll
        for (int h = 0; h < FH_; h++) f[h] = xf[h * CCH];
    }

    const float* wbase = g_wts + (size_t)blk * DD * FH_;
    const int*   bbase = g_binh + (size_t)blk * DD * FH_;
    float* ob = out + ((size_t)b * CCH + c) * (NZ_ * NX0_);

    for (int d = wg; d < DD; d += 8) {
        int fl = g_flags[blk * DD + d];
        if (fl == 0) continue;
        if (fl == 1) {
            const float4* wr = (const float4*)(wbase + d * FH_);  // broadcast
            float a0 = 0.f, a1 = 0.f, a2 = 0.f, a3 = 0.f;
            float a4 = 0.f, a5 = 0.f, a6 = 0.f, a7 = 0.f;
#pragma unroll
            for (int k = 0; k < 8; k += 2) {
                float4 u = wr[k];
                float4 v = wr[k + 1];
                a0 = __fmaf_rn(u.x, f[4 * k + 0], a0);
                a1 = __fmaf_rn(u.y, f[4 * k + 1], a1);
                a2 = __fmaf_rn(u.z, f[4 * k + 2], a2);
                a3 = __fmaf_rn(u.w, f[4 * k + 3], a3);
                a4 = __fmaf_rn(v.x, f[4 * k + 4], a4);
                a5 = __fmaf_rn(v.y, f[4 * k + 5], a5);
                a6 = __fmaf_rn(v.z, f[4 * k + 6], a6);
                a7 = __fmaf_rn(v.w, f[4 * k + 7], a7);
            }
            atomicAdd(ob + g_binsp[blk * DD + d],
                      ((a0 + a1) + (a2 + a3)) + ((a4 + a5) + (a6 + a7)));
        } else {
            // generic fallback: per-h scatter
#pragma unroll
            for (int h = 0; h < FH_; h++) {
                float wv = wbase[d * FH_ + h];
                if (wv != 0.f) atomicAdd(ob + bbase[d * FH_ + h], wv * f[h]);
            }
        }
    }
}

// ---------------------------------------------------------------------------
extern "C" void kernel_launch(void* const* d_in, const int* in_sizes, int n_in,
                              void* d_out, int out_size) {
    const float* x       = (const float*)d_in[0];
    const float* intrins = (const float*)d_in[1];
    const float* rots    = (const float*)d_in[2];
    const float* trans   = (const float*)d_in[3];
    float* out = (float*)d_out;

    dim3 tgrid(105, 3, B_);
    lss_T<<<tgrid, 256>>>(x);

    dim3 agrid(FW_, B_);
    lss_mainA<<<agrid, 256>>>(intrins, rots, trans, out);

    dim3 bgrid(FW_, B_, 2);
    lss_mainB<<<bgrid, 256>>>(out);
}

// round 16
// speedup vs baseline: 1.3805x; 1.3805x over previous
#include <cuda_runtime.h>
#include <cstdint>

// Problem constants (from reference)
#define DD   41
#define CCH  64
#define CHT  105          // DD + CCH
#define FH_  32
#define FW_  88
#define B_   4
#define NX0_ 200
#define NZ_  200
#define COLH (CHT * FH_)  // 3360 floats per (b,w) column
#define FOFF (DD * FH_)   // 1312: feature slab offset within a column
#define OUTN  (B_ * CCH * NZ_ * NX0_)   // 10,240,000 floats

// Static scratch: per (b,w) column = [logits d*32+h (1312)] [features h*64+c (2048)]
__device__ float g_xT[(size_t)B_ * FW_ * COLH];   // 4.73 MB

// ---------------------------------------------------------------------------
// Kernel 1 (R14-proven): fused (a) zero-fill of out and (b) layout transform.
// grid (105, 3, 4) x 256 thr. Zero-fill drains under the transform's latency.
// ---------------------------------------------------------------------------
__global__ __launch_bounds__(256) void lss_prep(const float* __restrict__ x,
                                                float* __restrict__ out) {
    __shared__ float tile[32][33];
    const int tx  = threadIdx.x & 31;
    const int ty  = threadIdx.x >> 5;
    const int tid = threadIdx.x;

    // (a) zero my slice of out (float4, grid-strided)
    {
        const int nblk = gridDim.x * gridDim.y * gridDim.z;          // 1260
        const int lin  = (blockIdx.z * gridDim.y + blockIdx.y) * gridDim.x
                       + blockIdx.x;
        float4* o4 = (float4*)out;
        const int n4 = OUTN / 4;
        const float4 z4 = make_float4(0.f, 0.f, 0.f, 0.f);
        for (int i = lin * 256 + tid; i < n4; i += nblk * 256) o4[i] = z4;
    }

    const int b  = blockIdx.z;
    const int c0 = blockIdx.y * 32;   // w-tile base
    const float* xb = x + (size_t)b * COLH * FW_;
    float* xt = g_xT + (size_t)b * FW_ * COLH;

    if (blockIdx.x < 41) {
        // (b1) logit tile -> xT[b][w][d*32+h]
        const int r0 = blockIdx.x * 32;
#pragma unroll
        for (int i = ty; i < 32; i += 8) {
            int r = r0 + i, c = c0 + tx;
            if (c < FW_) tile[i][tx] = xb[(size_t)r * FW_ + c];
        }
        __syncthreads();
#pragma unroll
        for (int i = ty; i < 32; i += 8) {
            int w = c0 + i, r = r0 + tx;
            if (w < FW_) xt[(size_t)w * COLH + r] = tile[tx][i];
        }
    } else {
        // (b2) feature tile (h, cgroup) -> xT[b][w][1312 + h*64 + c]
        const int idx = blockIdx.x - 41;      // 0..63
        const int h   = idx >> 1;
        const int cg  = idx & 1;
#pragma unroll
        for (int i = ty; i < 32; i += 8) {
            int row = (DD + cg * 32 + i) * FH_ + h;
            int c = c0 + tx;
            if (c < FW_) tile[i][tx] = xb[(size_t)row * FW_ + c];
        }
        __syncthreads();
#pragma unroll
        for (int j = ty; j < 32; j += 8) {
            int w = c0 + j;
            if (w < FW_)
                xt[(size_t)w * COLH + FOFF + h * CCH + cg * 32 + tx] = tile[tx][j];
        }
    }
}

// ---------------------------------------------------------------------------
// Kernel 2: main. One block per (w, b), 256 thr. TWO barriers total.
//  P1 : logits DIRECT to registers lg[6] (coalesced, lane = h);
//       PARALLEL inv3; NO logit smem pass
//  P2 : softmax partials in regs -> pm/ps; barrier; per-warp redundant
//       scale computation (bit-identical, no smem, no 2nd barrier)
//  Pf : f[32] coalesced LDGs (latency covered by P3)
//  P3 : geometry per (d,h); single smem write of final weight; ballots
//  P4 : warp=(dg,chalf), lane=c; broadcast LDS.128 weights; 8 accumulators;
//       ONE REDG per (d, channel).  [R14-proven]
// ---------------------------------------------------------------------------
__global__ __launch_bounds__(256, 3) void lss_main(
    const float* __restrict__ intrins,
    const float* __restrict__ rots,
    const float* __restrict__ trans,
    float* __restrict__ out)
{
    __shared__ float wts[DD][FH_];      // FINAL masked weights (written in P3)
    __shared__ float pm[8][FH_];        // per-group max
    __shared__ float ps[8][FH_];        // per-group sum
    __shared__ int   binsp[DD];
    __shared__ int   flags[DD];         // 0 = no kept, 1 = uniform, 2 = mixed
    __shared__ int   binh[DD][FH_];
    __shared__ float iR[9], iK[9], tv[3];

    const int w    = blockIdx.x;
    const int b    = blockIdx.y;
    const int tid  = threadIdx.x;
    const int lane = tid & 31;
    const int wg   = tid >> 5;                 // 0..7
    const int c    = ((wg & 1) << 5) + lane;   // phase-4 channel
    const int dg   = wg >> 1;                  // phase-4 d-subgroup (0..3)

    const float* xt = g_xT + ((size_t)b * FW_ + w) * COLH;

    // P1: logits direct to registers. Thread (wg, lane): d = wg + 8k.
    // Warp-load k: 32 consecutive floats (lane = h) => one 128B line each.
    float lg[6];
#pragma unroll
    for (int k = 0; k < 6; k++) {
        int d = wg + 8 * k;
        if (d < DD) lg[k] = xt[d * FH_ + lane];
    }

    // P1b: PARALLEL 3x3 inversions (one correctly-rounded division each;
    // bit-identical to serial adjugate form).
    if (tid < 18) {
        const int which = tid / 9;              // 0 = rots, 1 = intrins
        const int e     = tid % 9;
        const float* mm = which ? (intrins + b * 9) : (rots + b * 9);
        float a0 = mm[0], a1 = mm[1], a2 = mm[2];
        float a3 = mm[3], a4 = mm[4], a5 = mm[5];
        float a6 = mm[6], a7 = mm[7], a8 = mm[8];
        float c00 = a4 * a8 - a5 * a7;
        float c01 = a5 * a6 - a3 * a8;
        float c02 = a3 * a7 - a4 * a6;
        float det = a0 * c00 + a1 * c01 + a2 * c02;
        float num;
        switch (e) {
            case 0: num = c00; break;
            case 1: num = a2 * a7 - a1 * a8; break;
            case 2: num = a1 * a5 - a2 * a4; break;
            case 3: num = c01; break;
            case 4: num = a0 * a8 - a2 * a6; break;
            case 5: num = a2 * a3 - a0 * a5; break;
            case 6: num = c02; break;
            case 7: num = a1 * a6 - a0 * a7; break;
            default: num = a0 * a4 - a1 * a3; break;
        }
        float r = __fdiv_rn(num, det);
        if (which) iK[e] = r; else iR[e] = r;
    }
    if (tid < 3) tv[tid] = trans[b * 3 + tid];

    // P2a: per-thread softmax partials, all in registers.
    {
        float m_t = -3.402823466e38f;
#pragma unroll
        for (int k = 0; k < 6; k++)
            if (wg + 8 * k < DD) m_t = fmaxf(m_t, lg[k]);
        float s_t = 0.f;
#pragma unroll
        for (int k = 0; k < 6; k++)
            if (wg + 8 * k < DD) { lg[k] = __expf(lg[k] - m_t); s_t += lg[k]; }
        pm[wg][lane] = m_t;
        ps[wg][lane] = s_t;
    }
    __syncthreads();    // barrier 1: pm/ps + iR/iK/tv visible

    // P2b: per-warp redundant scale (identical expression/order for all warps
    // => bit-identical). No smem write, no extra barrier.
    float sc;
    {
        float m = pm[0][lane];
#pragma unroll
        for (int g = 1; g < 8; g++) m = fmaxf(m, pm[g][lane]);
        float s = 0.f;
#pragma unroll
        for (int g = 0; g < 8; g++) s += ps[g][lane] * __expf(pm[g][lane] - m);
        float rinv = __frcp_rn(s);
        sc = __expf(pm[wg][lane] - m) * rinv;
    }

    // Pf: feature loads (coalesced: lanes = consecutive c => one 128B line
    // per warp-load). Consumed in P4; latency covered by P3's ALU.
    float f[FH_];
    {
        const float* xf = xt + FOFF + c;
#pragma unroll
        for (int h = 0; h < FH_; h++) f[h] = xf[h * CCH];
    }

    // P3: geometry. Thread (wg, lane): d = wg + 8k; lane = h.
    {
        const float xs = (float)w    * (703.0f / 87.0f);
        const float ys = (float)lane * (255.0f / 31.0f);
        const float r00 = iR[0], r01 = iR[1], r02 = iR[2];
        const float r10 = iR[3], r11 = iR[4], r12 = iR[5];
        const float r20 = iR[6], r21 = iR[7], r22 = iR[8];
        const float k00 = iK[0], k01 = iK[1], k02 = iK[2];
        const float k10 = iK[3], k11 = iK[4], k12 = iK[5];
        const float k20 = iK[6], k21 = iK[7], k22 = iK[8];
        const float t0 = tv[0], t1 = tv[1], t2 = tv[2];
        const float p0 = xs - t0, p1 = ys - t1;

#pragma unroll
        for (int k = 0; k < 6; k++) {
            int d = wg + 8 * k;
            if (d >= DD) break;
            float p2 = (4.0f + (float)d) - t2;
            float q0 = __fmaf_rn(r00, p0, __fmaf_rn(r01, p1, r02 * p2));
            float q1 = __fmaf_rn(r10, p0, __fmaf_rn(r11, p1, r12 * p2));
            float q2 = __fmaf_rn(r20, p0, __fmaf_rn(r21, p1, r22 * p2));
            float s0 = q0 * q2, s1 = q1 * q2, s2 = q2;
            float g0 = __fmaf_rn(k00, s0, __fmaf_rn(k01, s1, k02 * s2));
            float g1 = __fmaf_rn(k10, s0, __fmaf_rn(k11, s1, k12 * s2));
            float g2 = __fmaf_rn(k20, s0, __fmaf_rn(k21, s1, k22 * s2));
            // truncation toward zero matches astype(int32)
            int c0i = (int)((g0 + 50.0f) / 0.5f);
            int c1i = (int)((g1 + 10.0f) / 20.0f);
            int c2i = (int)(g2 / 0.25f);
            bool kept = (c0i >= 0) & (c0i < NX0_) & (c1i >= 0) & (c1i < 1) &
                        (c2i >= 0) & (c2i < NZ_);
            int sp = c2i * NX0_ + c0i;
            binh[d][lane] = sp;
            wts[d][lane] = kept ? lg[k] * sc : 0.0f;   // single smem write

            unsigned km = __ballot_sync(0xffffffffu, kept);
            int fl = 0;
            if (km) {
                int src = __ffs(km) - 1;
                int lsp = __shfl_sync(0xffffffffu, sp, src);
                bool ok = (!kept) || (sp == lsp);
                fl = __all_sync(0xffffffffu, ok) ? 1 : 2;
                if (lane == 0) binsp[d] = lsp;
            }
            if (lane == 0) flags[d] = fl;
        }
    }
    __syncthreads();    // barrier 2: wts/binh/flags/binsp visible

    // P4: matvec + scatter (R14-proven). f in regs; wts rows broadcast
    // LDS.128; 8 independent accumulators; one REDG per (d, channel).
    {
        float* ob = out + ((size_t)b * CCH + c) * (NZ_ * NX0_);
        for (int d = dg; d < DD; d += 4) {
            int fl = flags[d];
            if (fl == 0) continue;
            if (fl == 1) {
                const float4* wr = (const float4*)&wts[d][0];
                float a0 = 0.f, a1 = 0.f, a2 = 0.f, a3 = 0.f;
                float a4 = 0.f, a5 = 0.f, a6 = 0.f, a7 = 0.f;
#pragma unroll
                for (int k = 0; k < 8; k += 2) {
                    float4 u = wr[k];
                    float4 v = wr[k + 1];
                    a0 = __fmaf_rn(u.x, f[4 * k + 0], a0);
                    a1 = __fmaf_rn(u.y, f[4 * k + 1], a1);
                    a2 = __fmaf_rn(u.z, f[4 * k + 2], a2);
                    a3 = __fmaf_rn(u.w, f[4 * k + 3], a3);
                    a4 = __fmaf_rn(v.x, f[4 * k + 4], a4);
                    a5 = __fmaf_rn(v.y, f[4 * k + 5], a5);
                    a6 = __fmaf_rn(v.z, f[4 * k + 6], a6);
                    a7 = __fmaf_rn(v.w, f[4 * k + 7], a7);
                }
                atomicAdd(ob + binsp[d],
                          ((a0 + a1) + (a2 + a3)) + ((a4 + a5) + (a6 + a7)));
            } else {
                // generic fallback: per-h scatter
#pragma unroll
                for (int h = 0; h < FH_; h++) {
                    float wv = wts[d][h];
                    if (wv != 0.f) atomicAdd(ob + binh[d][h], wv * f[h]);
                }
            }
        }
    }
}

// ---------------------------------------------------------------------------
extern "C" void kernel_launch(void* const* d_in, const int* in_sizes, int n_in,
                              void* d_out, int out_size) {
    const float* x       = (const float*)d_in[0];
    const float* intrins = (const float*)d_in[1];
    const float* rots    = (const float*)d_in[2];
    const float* trans   = (const float*)d_in[3];
    float* out = (float*)d_out;

    // fused zero-fill + layout transform (R14-proven)
    dim3 pgrid(105, 3, B_);
    lss_prep<<<pgrid, 256>>>(x, out);

    dim3 mgrid(FW_, B_);
    lss_main<<<mgrid, 256>>>(intrins, rots, trans, out);
}